// round 13
// baseline (speedup 1.0000x reference)
#include <cuda_runtime.h>
#include <cuda_fp16.h>
#include <stdint.h>

#define NN 100000
#define EE 800000
#define HD 128
#define PITCH 136   // padded smem row (fp16 elems) -> conflict-free LDSM

#define GEMM_BLKS 3126            // 1563 row-blocks x 2 (featsrc/skip)
#define DEG_BLKS  3125            // 800000 / 256
#define FAT_BLKS  (GEMM_BLKS + DEG_BLKS)

// ---------------- scratch (static device memory; no allocs) ----------------
__device__ float g_featsrc[NN * HD]; // projected features, fp32 (L2-resident)
__device__ float g_skip[NN * HD];
__device__ float g_el[NN * 4];
__device__ float g_er[NN * 4];
__device__ int   g_deg[NN];          // zero-init; k_scan re-zeroes after read
__device__ int   g_rowptr[NN];       // rebuilt every replay; consumed by fill
__device__ int   g_coff[EE];         // CSR: src BYTE offset (s*512)
__device__ float g_eledge[EE * 4];   // CSR: el[src] per edge (float4)
__device__ int   g_aggflag[128];     // lookback: agg+1 published, 0 = not ready

// ---------------- mma helpers -----------------------------------------------
__device__ __forceinline__ void ldsm4(uint32_t* d, const void* p) {
    uint32_t a = (uint32_t)__cvta_generic_to_shared(p);
    asm volatile("ldmatrix.sync.aligned.m8n8.x4.shared.b16 {%0,%1,%2,%3}, [%4];"
                 : "=r"(d[0]), "=r"(d[1]), "=r"(d[2]), "=r"(d[3]) : "r"(a));
}

__device__ __forceinline__ void mma_fp16(float* c, const uint32_t* a,
                                         uint32_t b0, uint32_t b1) {
    asm volatile(
        "mma.sync.aligned.m16n8k16.row.col.f32.f16.f16.f32 "
        "{%0,%1,%2,%3}, {%4,%5,%6,%7}, {%8,%9}, {%0,%1,%2,%3};"
        : "+f"(c[0]), "+f"(c[1]), "+f"(c[2]), "+f"(c[3])
        : "r"(a[0]), "r"(a[1]), "r"(a[2]), "r"(a[3]), "r"(b0), "r"(b1));
}

// ---------------- K1: FAT kernel -- fp16 GEMM  ||  degree count -------------
// Blocks [0, GEMM_BLKS): M=64 x N=128 GEMM; pair (2k, 2k+1) shares the A tile.
//   nblk=0 -> featsrc (fp32) + fused el/er;  nblk=1 -> skip (fp32).
// Blocks [GEMM_BLKS, FAT_BLKS): count in-degrees + clear lookback flags.
__global__ void __launch_bounds__(256, 3) k_fat(
        const float* __restrict__ feat,
        const float* __restrict__ attn_l, const float* __restrict__ attn_r,
        const float* __restrict__ W_src, const float* __restrict__ b_src,
        const float* __restrict__ W_skip, const float* __restrict__ b_skip,
        const int* __restrict__ dst) {
    if (blockIdx.x >= GEMM_BLKS) {
        int b = blockIdx.x - GEMM_BLKS;
        if (b == 0 && threadIdx.x < 128) g_aggflag[threadIdx.x] = 0;
        int e = b * 256 + threadIdx.x;
        if (e < EE) atomicAdd(&g_deg[dst[e]], 1);
        return;
    }

    extern __shared__ __half smem[];
    __half* sA = smem;                      // 64 x PITCH
    __half* sB = sA + 64 * PITCH;           // 128 x PITCH
    __shared__ float sEl[4][64];
    __shared__ float sEr[4][64];

    const int t = threadIdx.x;
    const int nblk = blockIdx.x & 1;
    const int row0 = (blockIdx.x >> 1) * 64;
    const float* W = nblk ? W_skip : W_src;
    const float* bias = nblk ? b_skip : b_src;

    // ---- A tile (fp32 -> fp16): 64x128 = 2048 float4, 256 thr x 8 ----
#pragma unroll
    for (int i = 0; i < 8; i++) {
        int id = t + i * 256;             // 0..2047
        int r = id >> 5;                  // 0..63
        int q = (id & 31) << 2;           // 0..124
        float4 v = make_float4(0.f, 0.f, 0.f, 0.f);
        if (row0 + r < NN)
            v = *(const float4*)&feat[(size_t)(row0 + r) * 128 + q];
        __half2* p = (__half2*)&sA[r * PITCH + q];
        p[0] = __floats2half2_rn(v.x, v.y);
        p[1] = __floats2half2_rn(v.z, v.w);
    }
    // ---- B tile (fp32 W -> fp16): 128x128 = 4096 float4, 256 thr x 16 ------
#pragma unroll
    for (int i = 0; i < 16; i++) {
        int id = t + i * 256;             // 0..4095
        int r = id >> 5;                  // 0..127
        int q = (id & 31) << 2;
        float4 v = *(const float4*)&W[(size_t)r * 128 + q];
        __half2* p = (__half2*)&sB[r * PITCH + q];
        p[0] = __floats2half2_rn(v.x, v.y);
        p[1] = __floats2half2_rn(v.z, v.w);
    }
    __syncthreads();

    // ---- warp tiling: 8 warps in 2(M) x 4(N); each 32(M) x 32(N) ----
    const int wid = t >> 5, lane = t & 31;
    const int m0w = (wid >> 2) * 32;
    const int n0w = (wid & 3) * 32;

    float acc[2][4][4];
#pragma unroll
    for (int mt = 0; mt < 2; mt++)
#pragma unroll
        for (int nt = 0; nt < 4; nt++)
#pragma unroll
            for (int f = 0; f < 4; f++) acc[mt][nt][f] = 0.f;

#pragma unroll
    for (int kc = 0; kc < 8; kc++) {
        const int k0 = kc * 16;
        uint32_t a[2][4];
#pragma unroll
        for (int mt = 0; mt < 2; mt++) {
            int r = m0w + mt * 16 + (lane & 7) + ((lane >> 3) & 1) * 8;
            int c = k0 + (lane >> 4) * 8;
            ldsm4(a[mt], &sA[r * PITCH + c]);
        }
        uint32_t b[2][4];
#pragma unroll
        for (int np = 0; np < 2; np++) {
            int r = n0w + np * 16 + (lane & 7) + (lane >> 4) * 8;
            int c = k0 + ((lane >> 3) & 1) * 8;
            ldsm4(b[np], &sB[r * PITCH + c]);
        }
#pragma unroll
        for (int mt = 0; mt < 2; mt++)
#pragma unroll
            for (int nt = 0; nt < 4; nt++)
                mma_fp16(acc[mt][nt], a[mt],
                         b[nt >> 1][(nt & 1) * 2], b[nt >> 1][(nt & 1) * 2 + 1]);
    }

    // ---- epilogue: bias + fp32 store; fused el/er for nblk==0 ---------------
    float* outp = nblk ? g_skip : g_featsrc;
    const int g = lane >> 2, c2 = (lane & 3) * 2;
    const int head = wid & 3;      // this warp's 32 cols = one head
    float elp[2][2] = {{0.f, 0.f}, {0.f, 0.f}};
    float erp[2][2] = {{0.f, 0.f}, {0.f, 0.f}};
#pragma unroll
    for (int mt = 0; mt < 2; mt++) {
        int rbase = row0 + m0w + mt * 16 + g;
#pragma unroll
        for (int nt = 0; nt < 4; nt++) {
            int col = n0w + nt * 8 + c2;
            float b0 = bias[col];
            float b1 = bias[col + 1];
            float f0 = acc[mt][nt][0] + b0, f1 = acc[mt][nt][1] + b1;
            float f2 = acc[mt][nt][2] + b0, f3 = acc[mt][nt][3] + b1;
            if (rbase < NN)
                *(float2*)&outp[(size_t)rbase * 128 + col] = make_float2(f0, f1);
            if (rbase + 8 < NN)
                *(float2*)&outp[(size_t)(rbase + 8) * 128 + col] = make_float2(f2, f3);
            if (nblk == 0) {
                float al0 = attn_l[col], al1 = attn_l[col + 1];
                float ar0 = attn_r[col], ar1 = attn_r[col + 1];
                elp[mt][0] += f0 * al0 + f1 * al1;
                elp[mt][1] += f2 * al0 + f3 * al1;
                erp[mt][0] += f0 * ar0 + f1 * ar1;
                erp[mt][1] += f2 * ar0 + f3 * ar1;
            }
        }
    }
    if (nblk == 0) {
        // reduce across the lane quad (lanes sharing g)
#pragma unroll
        for (int mt = 0; mt < 2; mt++)
#pragma unroll
            for (int hf = 0; hf < 2; hf++) {
                elp[mt][hf] += __shfl_xor_sync(0xffffffffu, elp[mt][hf], 1);
                elp[mt][hf] += __shfl_xor_sync(0xffffffffu, elp[mt][hf], 2);
                erp[mt][hf] += __shfl_xor_sync(0xffffffffu, erp[mt][hf], 1);
                erp[mt][hf] += __shfl_xor_sync(0xffffffffu, erp[mt][hf], 2);
            }
        if ((lane & 3) == 0) {
#pragma unroll
            for (int mt = 0; mt < 2; mt++)
#pragma unroll
                for (int hf = 0; hf < 2; hf++) {
                    int lr = m0w + mt * 16 + g + hf * 8;   // 0..63
                    sEl[head][lr] = elp[mt][hf];
                    sEr[head][lr] = erp[mt][hf];
                }
        }
        __syncthreads();
        int lr = t >> 2, h = t & 3;   // 64 rows x 4 heads
        if (row0 + lr < NN) {
            g_el[(row0 + lr) * 4 + h] = sEl[h][lr];
            g_er[(row0 + lr) * 4 + h] = sEr[h][lr];
        }
    }
}

// ---------------- K2: single-launch decoupled-lookback scan ------------------
__global__ void __launch_bounds__(1024) k_scan() {
    __shared__ int wsum[32];
    __shared__ int s_off;
    const int t = threadIdx.x;
    const int b = blockIdx.x;
    const int lane = t & 31, w = t >> 5;
    if (t == 0) s_off = 0;
    const int i = b * 1024 + t;
    int v = (i < NN) ? g_deg[i] : 0;
    if (i < NN) g_deg[i] = 0;             // reset for next replay
    int x = v;
#pragma unroll
    for (int off = 1; off < 32; off <<= 1) {
        int y = __shfl_up_sync(0xffffffffu, x, off);
        if (lane >= off) x += y;
    }
    if (lane == 31) wsum[w] = x;
    __syncthreads();
    if (w == 0) {
        int y = wsum[lane];
#pragma unroll
        for (int off = 1; off < 32; off <<= 1) {
            int z = __shfl_up_sync(0xffffffffu, y, off);
            if (lane >= off) y += z;
        }
        wsum[lane] = y;
    }
    __syncthreads();
    int incl = x + (w > 0 ? wsum[w - 1] : 0);     // block-inclusive prefix
    if (t == 1023) {                               // publish block aggregate
        int agg = incl + 1;
        asm volatile("st.global.release.gpu.b32 [%0], %1;"
                     :: "l"(&g_aggflag[b]), "r"(agg) : "memory");
    }
    if (t < b) {                                   // lookback (b <= 97 < 1024)
        int y;
        do {
            asm volatile("ld.global.acquire.gpu.b32 %0, [%1];"
                         : "=r"(y) : "l"(&g_aggflag[t]) : "memory");
        } while (y == 0);
        atomicAdd(&s_off, y - 1);
    }
    __syncthreads();
    if (i < NN) g_rowptr[i] = s_off + incl - v;   // global exclusive prefix
}

// ---------------- K3: fill CSR + pre-stage per-edge el ----------------------
// Writes src byte-offset (s*512) and el[src] float4 per CSR slot so k_node
// needs zero scattered el loads and no src-index multiply.
__global__ void k_fill(const int* __restrict__ src, const int* __restrict__ dst) {
    int i = blockIdx.x * blockDim.x + threadIdx.x;
    if (i < EE) {
        int s = src[i];
        float4 el4 = *(const float4*)&g_el[s * 4];
        int slot = atomicAdd(&g_rowptr[dst[i]], 1);
        g_coff[slot] = s * 512;            // byte offset into g_featsrc
        *(float4*)&g_eledge[(size_t)slot * 4] = el4;
    }
}

// ---------------- K4: per-node softmax + aggregate + gate + LN + PReLU ------
// Shifted CSR: start = rowptr[n-1] (or 0), end = rowptr[n].
// Edge-ordered el (contiguous) + byte-offset gather (fp32, L2-resident).
__global__ void k_node(const float* __restrict__ W_gate, const float* __restrict__ b_gate,
                       const float* __restrict__ ln_g, const float* __restrict__ ln_b,
                       const float* __restrict__ prelu_a, float* __restrict__ out) {
    int gid = blockIdx.x * blockDim.x + threadIdx.x;
    int n = gid >> 5;
    int lane = threadIdx.x & 31;
    if (n >= NN) return;
    const int h = lane >> 3;

    int start = (n == 0) ? 0 : g_rowptr[n - 1];
    int end = g_rowptr[n];
    int deg = end - start;
    float erh = g_er[n * 4 + h];

    const char* fbase = (const char*)g_featsrc + lane * 16;
    const float* elp = g_eledge + h;

    float4 acc = make_float4(0.f, 0.f, 0.f, 0.f);
    float sumex = 0.f;
    int k = start;
    for (; k + 3 < end; k += 4) {
        int o0 = g_coff[k],     o1 = g_coff[k + 1];
        int o2 = g_coff[k + 2], o3 = g_coff[k + 3];
        float e0 = elp[(size_t)k * 4] + erh;
        float e1 = elp[(size_t)(k + 1) * 4] + erh;
        float e2 = elp[(size_t)(k + 2) * 4] + erh;
        float e3 = elp[(size_t)(k + 3) * 4] + erh;
        float4 f0 = *(const float4*)(fbase + o0);
        float4 f1 = *(const float4*)(fbase + o1);
        float4 f2 = *(const float4*)(fbase + o2);
        float4 f3 = *(const float4*)(fbase + o3);
        e0 = fmaxf(e0, 0.2f * e0);
        e1 = fmaxf(e1, 0.2f * e1);
        e2 = fmaxf(e2, 0.2f * e2);
        e3 = fmaxf(e3, 0.2f * e3);
        float x0 = __expf(e0), x1 = __expf(e1), x2 = __expf(e2), x3 = __expf(e3);
        sumex += x0 + x1 + x2 + x3;
        acc.x += x0 * f0.x + x1 * f1.x + x2 * f2.x + x3 * f3.x;
        acc.y += x0 * f0.y + x1 * f1.y + x2 * f2.y + x3 * f3.y;
        acc.z += x0 * f0.z + x1 * f1.z + x2 * f2.z + x3 * f3.z;
        acc.w += x0 * f0.w + x1 * f1.w + x2 * f2.w + x3 * f3.w;
    }
    for (; k < end; k++) {
        int o = g_coff[k];
        float e = elp[(size_t)k * 4] + erh;
        e = fmaxf(e, 0.2f * e);
        float ex = __expf(e);
        sumex += ex;
        float4 f = *(const float4*)(fbase + o);
        acc.x += ex * f.x; acc.y += ex * f.y;
        acc.z += ex * f.z; acc.w += ex * f.w;
    }
    float4 rst;
    if (deg > 0) {
        float inv = 1.0f / sumex;
        rst = make_float4(acc.x * inv, acc.y * inv, acc.z * inv, acc.w * inv);
    } else {
        rst = make_float4(0.f, 0.f, 0.f, 0.f);
    }

    float4 sk = *(const float4*)&g_skip[(size_t)n * 128 + 4 * lane];
    float4 w1 = *(const float4*)&W_gate[4 * lane];
    float4 w2 = *(const float4*)&W_gate[128 + 4 * lane];
    float4 w3 = *(const float4*)&W_gate[256 + 4 * lane];
    float gacc = rst.x * w1.x + rst.y * w1.y + rst.z * w1.z + rst.w * w1.w
               + sk.x * w2.x + sk.y * w2.y + sk.z * w2.z + sk.w * w2.w
               + (rst.x - sk.x) * w3.x + (rst.y - sk.y) * w3.y
               + (rst.z - sk.z) * w3.z + (rst.w - sk.w) * w3.w;
#pragma unroll
    for (int off = 16; off >= 1; off >>= 1)
        gacc += __shfl_xor_sync(0xffffffffu, gacc, off);
    float gate = 1.0f / (1.0f + __expf(-(gacc + b_gate[0])));
    float4 x = make_float4(gate * rst.x + (1.f - gate) * sk.x,
                           gate * rst.y + (1.f - gate) * sk.y,
                           gate * rst.z + (1.f - gate) * sk.z,
                           gate * rst.w + (1.f - gate) * sk.w);

    float s1 = x.x + x.y + x.z + x.w;
    float s2 = x.x * x.x + x.y * x.y + x.z * x.z + x.w * x.w;
#pragma unroll
    for (int off = 16; off >= 1; off >>= 1) {
        s1 += __shfl_xor_sync(0xffffffffu, s1, off);
        s2 += __shfl_xor_sync(0xffffffffu, s2, off);
    }
    float mean = s1 * (1.0f / 128.0f);
    float var = s2 * (1.0f / 128.0f) - mean * mean;
    float inv = rsqrtf(var + 1e-5f);
    float4 g4 = *(const float4*)&ln_g[4 * lane];
    float4 b4 = *(const float4*)&ln_b[4 * lane];
    float alpha = prelu_a[0];
    float y0 = (x.x - mean) * inv * g4.x + b4.x;
    float y1 = (x.y - mean) * inv * g4.y + b4.y;
    float y2 = (x.z - mean) * inv * g4.z + b4.z;
    float y3 = (x.w - mean) * inv * g4.w + b4.w;
    y0 = (y0 >= 0.f) ? y0 : alpha * y0;
    y1 = (y1 >= 0.f) ? y1 : alpha * y1;
    y2 = (y2 >= 0.f) ? y2 : alpha * y2;
    y3 = (y3 >= 0.f) ? y3 : alpha * y3;
    *(float4*)&out[(size_t)n * 128 + 4 * lane] = make_float4(y0, y1, y2, y3);
}

// ---------------- launcher ---------------------------------------------------
extern "C" void kernel_launch(void* const* d_in, const int* in_sizes, int n_in,
                              void* d_out, int out_size) {
    const float* feat    = (const float*)d_in[0];
    const int*   src     = (const int*)d_in[1];
    const int*   dst     = (const int*)d_in[2];
    const float* W_src   = (const float*)d_in[3];
    const float* b_src   = (const float*)d_in[4];
    const float* attn_l  = (const float*)d_in[5];
    const float* attn_r  = (const float*)d_in[6];
    const float* W_skip  = (const float*)d_in[7];
    const float* b_skip  = (const float*)d_in[8];
    const float* W_gate  = (const float*)d_in[9];
    const float* b_gate  = (const float*)d_in[10];
    const float* ln_g    = (const float*)d_in[11];
    const float* ln_b    = (const float*)d_in[12];
    const float* prelu_a = (const float*)d_in[13];
    float* out = (float*)d_out;

    // smem: (64 + 128) * PITCH * 2B = 52224
    const int FAT_SMEM = (64 + 128) * PITCH * (int)sizeof(__half);
    static int smem_set = 0;
    if (!smem_set) {
        cudaFuncSetAttribute(k_fat, cudaFuncAttributeMaxDynamicSharedMemorySize, FAT_SMEM);
        smem_set = 1;
    }

    k_fat<<<FAT_BLKS, 256, FAT_SMEM>>>(feat, attn_l, attn_r,
                                       W_src, b_src, W_skip, b_skip, dst);
    k_scan<<<98, 1024>>>();
    k_fill<<<(EE + 255) / 256, 256>>>(src, dst);
    k_node<<<(NN * 32 + 255) / 256, 256>>>(W_gate, b_gate, ln_g, ln_b, prelu_a, out);
}

// round 14
// speedup vs baseline: 1.0701x; 1.0701x over previous
#include <cuda_runtime.h>
#include <cuda_fp16.h>
#include <stdint.h>

#define NN 100000
#define EE 800000
#define HD 128
#define PITCH 136   // padded smem row (fp16 elems) -> conflict-free LDSM

#define GEMM_BLKS 3126            // 1563 row-blocks x 2 (featsrc/skip)
#define DEG_BLKS  3125            // 800000 / 256
#define FAT_BLKS  (GEMM_BLKS + DEG_BLKS)

// ---------------- scratch (static device memory; no allocs) ----------------
__device__ __half g_fsh[NN * HD];    // featsrc fp16 (gather payload)
__device__ float g_skip[NN * HD];
__device__ float g_el[NN * 4];
__device__ float g_er[NN * 4];
__device__ int   g_deg[NN];          // zero-init; k_scan re-zeroes after read
__device__ int   g_rowptr[NN];       // rebuilt every replay; consumed by fill
__device__ int   g_coff[EE];         // CSR: src BYTE offset into g_fsh (s*256)
__device__ float g_eexp[EE * 4];     // CSR: exp(leaky(el[src]+er[dst])) per head
__device__ int   g_aggflag[128];     // lookback: agg+1 published, 0 = not ready

// ---------------- mma helpers -----------------------------------------------
__device__ __forceinline__ void ldsm4(uint32_t* d, const void* p) {
    uint32_t a = (uint32_t)__cvta_generic_to_shared(p);
    asm volatile("ldmatrix.sync.aligned.m8n8.x4.shared.b16 {%0,%1,%2,%3}, [%4];"
                 : "=r"(d[0]), "=r"(d[1]), "=r"(d[2]), "=r"(d[3]) : "r"(a));
}

__device__ __forceinline__ void mma_fp16(float* c, const uint32_t* a,
                                         uint32_t b0, uint32_t b1) {
    asm volatile(
        "mma.sync.aligned.m16n8k16.row.col.f32.f16.f16.f32 "
        "{%0,%1,%2,%3}, {%4,%5,%6,%7}, {%8,%9}, {%0,%1,%2,%3};"
        : "+f"(c[0]), "+f"(c[1]), "+f"(c[2]), "+f"(c[3])
        : "r"(a[0]), "r"(a[1]), "r"(a[2]), "r"(a[3]), "r"(b0), "r"(b1));
}

// ---------------- K1: FAT kernel -- fp16 GEMM  ||  degree count -------------
// Blocks [0, GEMM_BLKS): M=64 x N=128 GEMM; pair (2k, 2k+1) shares the A tile.
//   nblk=0 -> featsrc(fp16) + fused el/er;  nblk=1 -> skip (fp32).
// Blocks [GEMM_BLKS, FAT_BLKS): count in-degrees + clear lookback flags.
__global__ void __launch_bounds__(256, 3) k_fat(
        const float* __restrict__ feat,
        const float* __restrict__ attn_l, const float* __restrict__ attn_r,
        const float* __restrict__ W_src, const float* __restrict__ b_src,
        const float* __restrict__ W_skip, const float* __restrict__ b_skip,
        const int* __restrict__ dst) {
    if (blockIdx.x >= GEMM_BLKS) {
        int b = blockIdx.x - GEMM_BLKS;
        if (b == 0 && threadIdx.x < 128) g_aggflag[threadIdx.x] = 0;
        int e = b * 256 + threadIdx.x;
        if (e < EE) atomicAdd(&g_deg[dst[e]], 1);
        return;
    }

    extern __shared__ __half smem[];
    __half* sA = smem;                      // 64 x PITCH
    __half* sB = sA + 64 * PITCH;           // 128 x PITCH
    __shared__ float sEl[4][64];
    __shared__ float sEr[4][64];

    const int t = threadIdx.x;
    const int nblk = blockIdx.x & 1;
    const int row0 = (blockIdx.x >> 1) * 64;
    const float* W = nblk ? W_skip : W_src;
    const float* bias = nblk ? b_skip : b_src;

    // ---- A tile (fp32 -> fp16): 64x128 = 2048 float4, 256 thr x 8 ----
#pragma unroll
    for (int i = 0; i < 8; i++) {
        int id = t + i * 256;             // 0..2047
        int r = id >> 5;                  // 0..63
        int q = (id & 31) << 2;           // 0..124
        float4 v = make_float4(0.f, 0.f, 0.f, 0.f);
        if (row0 + r < NN)
            v = *(const float4*)&feat[(size_t)(row0 + r) * 128 + q];
        __half2* p = (__half2*)&sA[r * PITCH + q];
        p[0] = __floats2half2_rn(v.x, v.y);
        p[1] = __floats2half2_rn(v.z, v.w);
    }
    // ---- B tile (fp32 W -> fp16): 128x128 = 4096 float4, 256 thr x 16 ------
#pragma unroll
    for (int i = 0; i < 16; i++) {
        int id = t + i * 256;             // 0..4095
        int r = id >> 5;                  // 0..127
        int q = (id & 31) << 2;
        float4 v = *(const float4*)&W[(size_t)r * 128 + q];
        __half2* p = (__half2*)&sB[r * PITCH + q];
        p[0] = __floats2half2_rn(v.x, v.y);
        p[1] = __floats2half2_rn(v.z, v.w);
    }
    __syncthreads();

    // ---- warp tiling: 8 warps in 2(M) x 4(N); each 32(M) x 32(N) ----
    const int wid = t >> 5, lane = t & 31;
    const int m0w = (wid >> 2) * 32;
    const int n0w = (wid & 3) * 32;

    float acc[2][4][4];
#pragma unroll
    for (int mt = 0; mt < 2; mt++)
#pragma unroll
        for (int nt = 0; nt < 4; nt++)
#pragma unroll
            for (int f = 0; f < 4; f++) acc[mt][nt][f] = 0.f;

#pragma unroll
    for (int kc = 0; kc < 8; kc++) {
        const int k0 = kc * 16;
        uint32_t a[2][4];
#pragma unroll
        for (int mt = 0; mt < 2; mt++) {
            int r = m0w + mt * 16 + (lane & 7) + ((lane >> 3) & 1) * 8;
            int c = k0 + (lane >> 4) * 8;
            ldsm4(a[mt], &sA[r * PITCH + c]);
        }
        uint32_t b[2][4];
#pragma unroll
        for (int np = 0; np < 2; np++) {
            int r = n0w + np * 16 + (lane & 7) + (lane >> 4) * 8;
            int c = k0 + ((lane >> 3) & 1) * 8;
            ldsm4(b[np], &sB[r * PITCH + c]);
        }
#pragma unroll
        for (int mt = 0; mt < 2; mt++)
#pragma unroll
            for (int nt = 0; nt < 4; nt++)
                mma_fp16(acc[mt][nt], a[mt],
                         b[nt >> 1][(nt & 1) * 2], b[nt >> 1][(nt & 1) * 2 + 1]);
    }

    // ---- epilogue: bias + store; fused el/er for nblk==0 --------------------
    const int g = lane >> 2, c2 = (lane & 3) * 2;
    const int head = wid & 3;      // this warp's 32 cols = one head
    float elp[2][2] = {{0.f, 0.f}, {0.f, 0.f}};
    float erp[2][2] = {{0.f, 0.f}, {0.f, 0.f}};
#pragma unroll
    for (int mt = 0; mt < 2; mt++) {
        int rbase = row0 + m0w + mt * 16 + g;
#pragma unroll
        for (int nt = 0; nt < 4; nt++) {
            int col = n0w + nt * 8 + c2;
            float b0 = bias[col];
            float b1 = bias[col + 1];
            float f0 = acc[mt][nt][0] + b0, f1 = acc[mt][nt][1] + b1;
            float f2 = acc[mt][nt][2] + b0, f3 = acc[mt][nt][3] + b1;
            if (nblk == 0) {
                if (rbase < NN)
                    *(__half2*)&g_fsh[(size_t)rbase * 128 + col] = __floats2half2_rn(f0, f1);
                if (rbase + 8 < NN)
                    *(__half2*)&g_fsh[(size_t)(rbase + 8) * 128 + col] = __floats2half2_rn(f2, f3);
                float al0 = attn_l[col], al1 = attn_l[col + 1];
                float ar0 = attn_r[col], ar1 = attn_r[col + 1];
                elp[mt][0] += f0 * al0 + f1 * al1;
                elp[mt][1] += f2 * al0 + f3 * al1;
                erp[mt][0] += f0 * ar0 + f1 * ar1;
                erp[mt][1] += f2 * ar0 + f3 * ar1;
            } else {
                if (rbase < NN)
                    *(float2*)&g_skip[(size_t)rbase * 128 + col] = make_float2(f0, f1);
                if (rbase + 8 < NN)
                    *(float2*)&g_skip[(size_t)(rbase + 8) * 128 + col] = make_float2(f2, f3);
            }
        }
    }
    if (nblk == 0) {
        // reduce across the lane quad (lanes sharing g)
#pragma unroll
        for (int mt = 0; mt < 2; mt++)
#pragma unroll
            for (int hf = 0; hf < 2; hf++) {
                elp[mt][hf] += __shfl_xor_sync(0xffffffffu, elp[mt][hf], 1);
                elp[mt][hf] += __shfl_xor_sync(0xffffffffu, elp[mt][hf], 2);
                erp[mt][hf] += __shfl_xor_sync(0xffffffffu, erp[mt][hf], 1);
                erp[mt][hf] += __shfl_xor_sync(0xffffffffu, erp[mt][hf], 2);
            }
        if ((lane & 3) == 0) {
#pragma unroll
            for (int mt = 0; mt < 2; mt++)
#pragma unroll
                for (int hf = 0; hf < 2; hf++) {
                    int lr = m0w + mt * 16 + g + hf * 8;   // 0..63
                    sEl[head][lr] = elp[mt][hf];
                    sEr[head][lr] = erp[mt][hf];
                }
        }
        __syncthreads();
        int lr = t >> 2, h = t & 3;   // 64 rows x 4 heads
        if (row0 + lr < NN) {
            g_el[(row0 + lr) * 4 + h] = sEl[h][lr];
            g_er[(row0 + lr) * 4 + h] = sEr[h][lr];
        }
    }
}

// ---------------- K2: single-launch decoupled-lookback scan ------------------
__global__ void __launch_bounds__(1024) k_scan() {
    __shared__ int wsum[32];
    __shared__ int s_off;
    const int t = threadIdx.x;
    const int b = blockIdx.x;
    const int lane = t & 31, w = t >> 5;
    if (t == 0) s_off = 0;
    const int i = b * 1024 + t;
    int v = (i < NN) ? g_deg[i] : 0;
    if (i < NN) g_deg[i] = 0;             // reset for next replay
    int x = v;
#pragma unroll
    for (int off = 1; off < 32; off <<= 1) {
        int y = __shfl_up_sync(0xffffffffu, x, off);
        if (lane >= off) x += y;
    }
    if (lane == 31) wsum[w] = x;
    __syncthreads();
    if (w == 0) {
        int y = wsum[lane];
#pragma unroll
        for (int off = 1; off < 32; off <<= 1) {
            int z = __shfl_up_sync(0xffffffffu, y, off);
            if (lane >= off) y += z;
        }
        wsum[lane] = y;
    }
    __syncthreads();
    int incl = x + (w > 0 ? wsum[w - 1] : 0);     // block-inclusive prefix
    if (t == 1023) {                               // publish block aggregate
        int agg = incl + 1;
        asm volatile("st.global.release.gpu.b32 [%0], %1;"
                     :: "l"(&g_aggflag[b]), "r"(agg) : "memory");
    }
    if (t < b) {                                   // lookback (b <= 97 < 1024)
        int y;
        do {
            asm volatile("ld.global.acquire.gpu.b32 %0, [%1];"
                         : "=r"(y) : "l"(&g_aggflag[t]) : "memory");
        } while (y == 0);
        atomicAdd(&s_off, y - 1);
    }
    __syncthreads();
    if (i < NN) g_rowptr[i] = s_off + incl - v;   // global exclusive prefix
}

// ---------------- K3: fill CSR + per-edge softmax numerators -----------------
// Computes exp(leaky(el[src]+er[dst])) for all 4 heads ONCE per edge (instead
// of 32x redundantly in k_node) and stages it edge-ordered with the source
// byte offset.
__global__ void k_fill(const int* __restrict__ src, const int* __restrict__ dst) {
    int i = blockIdx.x * blockDim.x + threadIdx.x;
    if (i < EE) {
        int s = src[i], d = dst[i];
        float4 el4 = *(const float4*)&g_el[s * 4];
        float4 er4 = *(const float4*)&g_er[d * 4];
        float e0 = el4.x + er4.x; e0 = fmaxf(e0, 0.2f * e0);
        float e1 = el4.y + er4.y; e1 = fmaxf(e1, 0.2f * e1);
        float e2 = el4.z + er4.z; e2 = fmaxf(e2, 0.2f * e2);
        float e3 = el4.w + er4.w; e3 = fmaxf(e3, 0.2f * e3);
        int slot = atomicAdd(&g_rowptr[d], 1);
        g_coff[slot] = s * 256;            // byte offset into g_fsh
        *(float4*)&g_eexp[(size_t)slot * 4] =
            make_float4(__expf(e0), __expf(e1), __expf(e2), __expf(e3));
    }
}

// ---------------- K4: per-node aggregate + gate + LN + PReLU ----------------
// Shifted CSR: start = rowptr[n-1] (or 0), end = rowptr[n].
// Per edge: broadcast coff, per-head exp (contiguous), fp16 feature gather.
__global__ void k_node(const float* __restrict__ W_gate, const float* __restrict__ b_gate,
                       const float* __restrict__ ln_g, const float* __restrict__ ln_b,
                       const float* __restrict__ prelu_a, float* __restrict__ out) {
    int gid = blockIdx.x * blockDim.x + threadIdx.x;
    int n = gid >> 5;
    int lane = threadIdx.x & 31;
    if (n >= NN) return;
    const int h = lane >> 3;

    int start = (n == 0) ? 0 : g_rowptr[n - 1];
    int end = g_rowptr[n];
    int deg = end - start;

    const char* fbase = (const char*)g_fsh + lane * 8;   // 4 halves per lane
    const float* exp_p = g_eexp + h;

    float4 acc = make_float4(0.f, 0.f, 0.f, 0.f);
    float sumex = 0.f;
    int k = start;
    for (; k + 3 < end; k += 4) {
        int o0 = g_coff[k],     o1 = g_coff[k + 1];
        int o2 = g_coff[k + 2], o3 = g_coff[k + 3];
        float x0 = exp_p[(size_t)k * 4];
        float x1 = exp_p[(size_t)(k + 1) * 4];
        float x2 = exp_p[(size_t)(k + 2) * 4];
        float x3 = exp_p[(size_t)(k + 3) * 4];
        uint2 u0 = *(const uint2*)(fbase + o0);
        uint2 u1 = *(const uint2*)(fbase + o1);
        uint2 u2 = *(const uint2*)(fbase + o2);
        uint2 u3 = *(const uint2*)(fbase + o3);
        sumex += x0 + x1 + x2 + x3;
        float2 a0 = __half22float2(*(__half2*)&u0.x), b0 = __half22float2(*(__half2*)&u0.y);
        float2 a1 = __half22float2(*(__half2*)&u1.x), b1 = __half22float2(*(__half2*)&u1.y);
        float2 a2 = __half22float2(*(__half2*)&u2.x), b2 = __half22float2(*(__half2*)&u2.y);
        float2 a3 = __half22float2(*(__half2*)&u3.x), b3 = __half22float2(*(__half2*)&u3.y);
        acc.x += x0 * a0.x + x1 * a1.x + x2 * a2.x + x3 * a3.x;
        acc.y += x0 * a0.y + x1 * a1.y + x2 * a2.y + x3 * a3.y;
        acc.z += x0 * b0.x + x1 * b1.x + x2 * b2.x + x3 * b3.x;
        acc.w += x0 * b0.y + x1 * b1.y + x2 * b2.y + x3 * b3.y;
    }
    for (; k < end; k++) {
        int o = g_coff[k];
        float ex = exp_p[(size_t)k * 4];
        uint2 u = *(const uint2*)(fbase + o);
        sumex += ex;
        float2 a = __half22float2(*(__half2*)&u.x), b = __half22float2(*(__half2*)&u.y);
        acc.x += ex * a.x; acc.y += ex * a.y;
        acc.z += ex * b.x; acc.w += ex * b.y;
    }
    float4 rst;
    if (deg > 0) {
        float inv = 1.0f / sumex;
        rst = make_float4(acc.x * inv, acc.y * inv, acc.z * inv, acc.w * inv);
    } else {
        rst = make_float4(0.f, 0.f, 0.f, 0.f);
    }

    float4 sk = *(const float4*)&g_skip[(size_t)n * 128 + 4 * lane];
    float4 w1 = *(const float4*)&W_gate[4 * lane];
    float4 w2 = *(const float4*)&W_gate[128 + 4 * lane];
    float4 w3 = *(const float4*)&W_gate[256 + 4 * lane];
    float gacc = rst.x * w1.x + rst.y * w1.y + rst.z * w1.z + rst.w * w1.w
               + sk.x * w2.x + sk.y * w2.y + sk.z * w2.z + sk.w * w2.w
               + (rst.x - sk.x) * w3.x + (rst.y - sk.y) * w3.y
               + (rst.z - sk.z) * w3.z + (rst.w - sk.w) * w3.w;
#pragma unroll
    for (int off = 16; off >= 1; off >>= 1)
        gacc += __shfl_xor_sync(0xffffffffu, gacc, off);
    float gate = 1.0f / (1.0f + __expf(-(gacc + b_gate[0])));
    float4 x = make_float4(gate * rst.x + (1.f - gate) * sk.x,
                           gate * rst.y + (1.f - gate) * sk.y,
                           gate * rst.z + (1.f - gate) * sk.z,
                           gate * rst.w + (1.f - gate) * sk.w);

    float s1 = x.x + x.y + x.z + x.w;
    float s2 = x.x * x.x + x.y * x.y + x.z * x.z + x.w * x.w;
#pragma unroll
    for (int off = 16; off >= 1; off >>= 1) {
        s1 += __shfl_xor_sync(0xffffffffu, s1, off);
        s2 += __shfl_xor_sync(0xffffffffu, s2, off);
    }
    float mean = s1 * (1.0f / 128.0f);
    float var = s2 * (1.0f / 128.0f) - mean * mean;
    float inv = rsqrtf(var + 1e-5f);
    float4 g4 = *(const float4*)&ln_g[4 * lane];
    float4 b4 = *(const float4*)&ln_b[4 * lane];
    float alpha = prelu_a[0];
    float y0 = (x.x - mean) * inv * g4.x + b4.x;
    float y1 = (x.y - mean) * inv * g4.y + b4.y;
    float y2 = (x.z - mean) * inv * g4.z + b4.z;
    float y3 = (x.w - mean) * inv * g4.w + b4.w;
    y0 = (y0 >= 0.f) ? y0 : alpha * y0;
    y1 = (y1 >= 0.f) ? y1 : alpha * y1;
    y2 = (y2 >= 0.f) ? y2 : alpha * y2;
    y3 = (y3 >= 0.f) ? y3 : alpha * y3;
    *(float4*)&out[(size_t)n * 128 + 4 * lane] = make_float4(y0, y1, y2, y3);
}

// ---------------- launcher ---------------------------------------------------
extern "C" void kernel_launch(void* const* d_in, const int* in_sizes, int n_in,
                              void* d_out, int out_size) {
    const float* feat    = (const float*)d_in[0];
    const int*   src     = (const int*)d_in[1];
    const int*   dst     = (const int*)d_in[2];
    const float* W_src   = (const float*)d_in[3];
    const float* b_src   = (const float*)d_in[4];
    const float* attn_l  = (const float*)d_in[5];
    const float* attn_r  = (const float*)d_in[6];
    const float* W_skip  = (const float*)d_in[7];
    const float* b_skip  = (const float*)d_in[8];
    const float* W_gate  = (const float*)d_in[9];
    const float* b_gate  = (const float*)d_in[10];
    const float* ln_g    = (const float*)d_in[11];
    const float* ln_b    = (const float*)d_in[12];
    const float* prelu_a = (const float*)d_in[13];
    float* out = (float*)d_out;

    // smem: (64 + 128) * PITCH * 2B = 52224
    const int FAT_SMEM = (64 + 128) * PITCH * (int)sizeof(__half);
    static int smem_set = 0;
    if (!smem_set) {
        cudaFuncSetAttribute(k_fat, cudaFuncAttributeMaxDynamicSharedMemorySize, FAT_SMEM);
        smem_set = 1;
    }

    k_fat<<<FAT_BLKS, 256, FAT_SMEM>>>(feat, attn_l, attn_r,
                                       W_src, b_src, W_skip, b_skip, dst);
    k_scan<<<98, 1024>>>();
    k_fill<<<(EE + 255) / 256, 256>>>(src, dst);
    k_node<<<(NN * 32 + 255) / 256, 256>>>(W_gate, b_gate, ln_g, ln_b, prelu_a, out);
}

// round 17
// speedup vs baseline: 1.1465x; 1.0714x over previous
#include <cuda_runtime.h>
#include <cuda_fp16.h>
#include <stdint.h>

#define NN 100000
#define EE 800000
#define HD 128
#define PITCH 136   // padded smem row (fp16 elems) -> conflict-free LDSM

#define GEMM_BLKS 3126            // 1563 row-blocks x 2 (featsrc/skip)
#define DEG_BLKS  3125            // 800000 / 256
#define FAT_BLKS  (GEMM_BLKS + DEG_BLKS)

// ---------------- scratch (static device memory; no allocs) ----------------
__device__ __half g_fsh[NN * HD];    // featsrc fp16 (gather payload)
__device__ float g_skip[NN * HD];
__device__ float g_el[NN * 4];
__device__ float g_er[NN * 4];
__device__ int   g_deg[NN];          // zero-init; k_scan re-zeroes after read
__device__ int   g_rowptr[NN];       // rebuilt every replay; consumed by fill
__device__ int   g_csrc[EE];         // CSR: src node id per slot
__device__ int   g_aggflag[128];     // lookback: agg+1 published, 0 = not ready

// ---------------- mma helpers -----------------------------------------------
__device__ __forceinline__ void ldsm4(uint32_t* d, const void* p) {
    uint32_t a = (uint32_t)__cvta_generic_to_shared(p);
    asm volatile("ldmatrix.sync.aligned.m8n8.x4.shared.b16 {%0,%1,%2,%3}, [%4];"
                 : "=r"(d[0]), "=r"(d[1]), "=r"(d[2]), "=r"(d[3]) : "r"(a));
}

__device__ __forceinline__ void mma_fp16(float* c, const uint32_t* a,
                                         uint32_t b0, uint32_t b1) {
    asm volatile(
        "mma.sync.aligned.m16n8k16.row.col.f32.f16.f16.f32 "
        "{%0,%1,%2,%3}, {%4,%5,%6,%7}, {%8,%9}, {%0,%1,%2,%3};"
        : "+f"(c[0]), "+f"(c[1]), "+f"(c[2]), "+f"(c[3])
        : "r"(a[0]), "r"(a[1]), "r"(a[2]), "r"(a[3]), "r"(b0), "r"(b1));
}

// ---------------- K1: FAT kernel -- fp16 GEMM  ||  degree count -------------
// Blocks [0, GEMM_BLKS): M=64 x N=128 GEMM; pair (2k, 2k+1) shares the A tile.
//   nblk=0 -> featsrc(fp16) + fused el/er;  nblk=1 -> skip (fp32).
// Blocks [GEMM_BLKS, FAT_BLKS): count in-degrees + clear lookback flags.
__global__ void __launch_bounds__(256, 3) k_fat(
        const float* __restrict__ feat,
        const float* __restrict__ attn_l, const float* __restrict__ attn_r,
        const float* __restrict__ W_src, const float* __restrict__ b_src,
        const float* __restrict__ W_skip, const float* __restrict__ b_skip,
        const int* __restrict__ dst) {
    if (blockIdx.x >= GEMM_BLKS) {
        int b = blockIdx.x - GEMM_BLKS;
        if (b == 0 && threadIdx.x < 128) g_aggflag[threadIdx.x] = 0;
        int e = b * 256 + threadIdx.x;
        if (e < EE) atomicAdd(&g_deg[dst[e]], 1);
        return;
    }

    extern __shared__ __half smem[];
    __half* sA = smem;                      // 64 x PITCH
    __half* sB = sA + 64 * PITCH;           // 128 x PITCH
    __shared__ float sEl[4][64];
    __shared__ float sEr[4][64];

    const int t = threadIdx.x;
    const int nblk = blockIdx.x & 1;
    const int row0 = (blockIdx.x >> 1) * 64;
    const float* W = nblk ? W_skip : W_src;
    const float* bias = nblk ? b_skip : b_src;

    // ---- A tile (fp32 -> fp16): 64x128 = 2048 float4, 256 thr x 8 ----
#pragma unroll
    for (int i = 0; i < 8; i++) {
        int id = t + i * 256;             // 0..2047
        int r = id >> 5;                  // 0..63
        int q = (id & 31) << 2;           // 0..124
        float4 v = make_float4(0.f, 0.f, 0.f, 0.f);
        if (row0 + r < NN)
            v = *(const float4*)&feat[(size_t)(row0 + r) * 128 + q];
        __half2* p = (__half2*)&sA[r * PITCH + q];
        p[0] = __floats2half2_rn(v.x, v.y);
        p[1] = __floats2half2_rn(v.z, v.w);
    }
    // ---- B tile (fp32 W -> fp16): 128x128 = 4096 float4, 256 thr x 16 ------
#pragma unroll
    for (int i = 0; i < 16; i++) {
        int id = t + i * 256;             // 0..4095
        int r = id >> 5;                  // 0..127
        int q = (id & 31) << 2;
        float4 v = *(const float4*)&W[(size_t)r * 128 + q];
        __half2* p = (__half2*)&sB[r * PITCH + q];
        p[0] = __floats2half2_rn(v.x, v.y);
        p[1] = __floats2half2_rn(v.z, v.w);
    }
    __syncthreads();

    // ---- warp tiling: 8 warps in 2(M) x 4(N); each 32(M) x 32(N) ----
    const int wid = t >> 5, lane = t & 31;
    const int m0w = (wid >> 2) * 32;
    const int n0w = (wid & 3) * 32;

    float acc[2][4][4];
#pragma unroll
    for (int mt = 0; mt < 2; mt++)
#pragma unroll
        for (int nt = 0; nt < 4; nt++)
#pragma unroll
            for (int f = 0; f < 4; f++) acc[mt][nt][f] = 0.f;

#pragma unroll
    for (int kc = 0; kc < 8; kc++) {
        const int k0 = kc * 16;
        uint32_t a[2][4];
#pragma unroll
        for (int mt = 0; mt < 2; mt++) {
            int r = m0w + mt * 16 + (lane & 7) + ((lane >> 3) & 1) * 8;
            int c = k0 + (lane >> 4) * 8;
            ldsm4(a[mt], &sA[r * PITCH + c]);
        }
        uint32_t b[2][4];
#pragma unroll
        for (int np = 0; np < 2; np++) {
            int r = n0w + np * 16 + (lane & 7) + (lane >> 4) * 8;
            int c = k0 + ((lane >> 3) & 1) * 8;
            ldsm4(b[np], &sB[r * PITCH + c]);
        }
#pragma unroll
        for (int mt = 0; mt < 2; mt++)
#pragma unroll
            for (int nt = 0; nt < 4; nt++)
                mma_fp16(acc[mt][nt], a[mt],
                         b[nt >> 1][(nt & 1) * 2], b[nt >> 1][(nt & 1) * 2 + 1]);
    }

    // ---- epilogue: bias + store; fused el/er for nblk==0 --------------------
    const int g = lane >> 2, c2 = (lane & 3) * 2;
    const int head = wid & 3;      // this warp's 32 cols = one head
    float elp[2][2] = {{0.f, 0.f}, {0.f, 0.f}};
    float erp[2][2] = {{0.f, 0.f}, {0.f, 0.f}};
#pragma unroll
    for (int mt = 0; mt < 2; mt++) {
        int rbase = row0 + m0w + mt * 16 + g;
#pragma unroll
        for (int nt = 0; nt < 4; nt++) {
            int col = n0w + nt * 8 + c2;
            float b0 = bias[col];
            float b1 = bias[col + 1];
            float f0 = acc[mt][nt][0] + b0, f1 = acc[mt][nt][1] + b1;
            float f2 = acc[mt][nt][2] + b0, f3 = acc[mt][nt][3] + b1;
            if (nblk == 0) {
                if (rbase < NN)
                    *(__half2*)&g_fsh[(size_t)rbase * 128 + col] = __floats2half2_rn(f0, f1);
                if (rbase + 8 < NN)
                    *(__half2*)&g_fsh[(size_t)(rbase + 8) * 128 + col] = __floats2half2_rn(f2, f3);
                float al0 = attn_l[col], al1 = attn_l[col + 1];
                float ar0 = attn_r[col], ar1 = attn_r[col + 1];
                elp[mt][0] += f0 * al0 + f1 * al1;
                elp[mt][1] += f2 * al0 + f3 * al1;
                erp[mt][0] += f0 * ar0 + f1 * ar1;
                erp[mt][1] += f2 * ar0 + f3 * ar1;
            } else {
                if (rbase < NN)
                    *(float2*)&g_skip[(size_t)rbase * 128 + col] = make_float2(f0, f1);
                if (rbase + 8 < NN)
                    *(float2*)&g_skip[(size_t)(rbase + 8) * 128 + col] = make_float2(f2, f3);
            }
        }
    }
    if (nblk == 0) {
        // reduce across the lane quad (lanes sharing g)
#pragma unroll
        for (int mt = 0; mt < 2; mt++)
#pragma unroll
            for (int hf = 0; hf < 2; hf++) {
                elp[mt][hf] += __shfl_xor_sync(0xffffffffu, elp[mt][hf], 1);
                elp[mt][hf] += __shfl_xor_sync(0xffffffffu, elp[mt][hf], 2);
                erp[mt][hf] += __shfl_xor_sync(0xffffffffu, erp[mt][hf], 1);
                erp[mt][hf] += __shfl_xor_sync(0xffffffffu, erp[mt][hf], 2);
            }
        if ((lane & 3) == 0) {
#pragma unroll
            for (int mt = 0; mt < 2; mt++)
#pragma unroll
                for (int hf = 0; hf < 2; hf++) {
                    int lr = m0w + mt * 16 + g + hf * 8;   // 0..63
                    sEl[head][lr] = elp[mt][hf];
                    sEr[head][lr] = erp[mt][hf];
                }
        }
        __syncthreads();
        int lr = t >> 2, h = t & 3;   // 64 rows x 4 heads
        if (row0 + lr < NN) {
            g_el[(row0 + lr) * 4 + h] = sEl[h][lr];
            g_er[(row0 + lr) * 4 + h] = sEr[h][lr];
        }
    }
}

// ---------------- K2: single-launch decoupled-lookback scan ------------------
__global__ void __launch_bounds__(1024) k_scan() {
    __shared__ int wsum[32];
    __shared__ int s_off;
    const int t = threadIdx.x;
    const int b = blockIdx.x;
    const int lane = t & 31, w = t >> 5;
    if (t == 0) s_off = 0;
    const int i = b * 1024 + t;
    int v = (i < NN) ? g_deg[i] : 0;
    if (i < NN) g_deg[i] = 0;             // reset for next replay
    int x = v;
#pragma unroll
    for (int off = 1; off < 32; off <<= 1) {
        int y = __shfl_up_sync(0xffffffffu, x, off);
        if (lane >= off) x += y;
    }
    if (lane == 31) wsum[w] = x;
    __syncthreads();
    if (w == 0) {
        int y = wsum[lane];
#pragma unroll
        for (int off = 1; off < 32; off <<= 1) {
            int z = __shfl_up_sync(0xffffffffu, y, off);
            if (lane >= off) y += z;
        }
        wsum[lane] = y;
    }
    __syncthreads();
    int incl = x + (w > 0 ? wsum[w - 1] : 0);     // block-inclusive prefix
    if (t == 1023) {                               // publish block aggregate
        int agg = incl + 1;
        asm volatile("st.global.release.gpu.b32 [%0], %1;"
                     :: "l"(&g_aggflag[b]), "r"(agg) : "memory");
    }
    if (t < b) {                                   // lookback (b <= 97 < 1024)
        int y;
        do {
            asm volatile("ld.global.acquire.gpu.b32 %0, [%1];"
                         : "=r"(y) : "l"(&g_aggflag[t]) : "memory");
        } while (y == 0);
        atomicAdd(&s_off, y - 1);
    }
    __syncthreads();
    if (i < NN) g_rowptr[i] = s_off + incl - v;   // global exclusive prefix
}

// ---------------- K3: fill CSR (atomics consume g_rowptr in place) ----------
__global__ void k_fill(const int* __restrict__ src, const int* __restrict__ dst) {
    int i = blockIdx.x * blockDim.x + threadIdx.x;
    if (i < EE) {
        int slot = atomicAdd(&g_rowptr[dst[i]], 1);
        g_csrc[slot] = src[i];
    }
}

// ---------------- K4: per-node aggregate + gate + LN + PReLU ----------------
// Shifted CSR: start = rowptr[n-1] (or 0), end = rowptr[n].
// Two-phase per 32-edge chunk: phase 1 = one lane per edge computes all 4
// heads' exp(leaky(el+er)) once (8x less redundant MUFU) and stages
// {w4, byte-offset} in smem; phase 2 = full-warp gather-accumulate with
// broadcast LDS reads. No extra global traffic (the R13/R14 mistake).
__global__ void __launch_bounds__(256) k_node(
        const float* __restrict__ W_gate, const float* __restrict__ b_gate,
        const float* __restrict__ ln_g, const float* __restrict__ ln_b,
        const float* __restrict__ prelu_a, float* __restrict__ out) {
    __shared__ float s_w[8][32][4];   // [warp][edge][head]
    __shared__ int   s_o[8][32];      // [warp][edge] byte offset into g_fsh

    int gid = blockIdx.x * blockDim.x + threadIdx.x;
    int n = gid >> 5;
    int lane = threadIdx.x & 31;
    int wid = (threadIdx.x >> 5);
    if (n >= NN) return;
    const int h = lane >> 3;

    int start = (n == 0) ? 0 : g_rowptr[n - 1];
    int end = g_rowptr[n];
    int deg = end - start;
    float4 er4 = *(const float4*)&g_er[n * 4];

    const char* fbase = (const char*)g_fsh + lane * 8;   // 4 halves per lane

    float4 acc = make_float4(0.f, 0.f, 0.f, 0.f);
    float sumex = 0.f;

    for (int base = start; base < end; base += 32) {
        int m = end - base; if (m > 32) m = 32;
        // ---- phase 1: one lane per edge ----
        if (lane < m) {
            int s = g_csrc[base + lane];
            float4 el4 = *(const float4*)&g_el[s * 4];
            float e0 = el4.x + er4.x; e0 = fmaxf(e0, 0.2f * e0);
            float e1 = el4.y + er4.y; e1 = fmaxf(e1, 0.2f * e1);
            float e2 = el4.z + er4.z; e2 = fmaxf(e2, 0.2f * e2);
            float e3 = el4.w + er4.w; e3 = fmaxf(e3, 0.2f * e3);
            *(float4*)&s_w[wid][lane][0] =
                make_float4(__expf(e0), __expf(e1), __expf(e2), __expf(e3));
            s_o[wid][lane] = s * 256;
        }
        __syncwarp();
        // ---- phase 2: full warp per edge ----
#pragma unroll 4
        for (int e = 0; e < m; e++) {
            float wv = s_w[wid][e][h];          // 4 distinct addrs -> broadcast
            int o = s_o[wid][e];                // 1 addr -> broadcast
            uint2 u = *(const uint2*)(fbase + o);
            sumex += wv;
            float2 a = __half22float2(*(__half2*)&u.x);
            float2 b = __half22float2(*(__half2*)&u.y);
            acc.x += wv * a.x; acc.y += wv * a.y;
            acc.z += wv * b.x; acc.w += wv * b.y;
        }
        __syncwarp();
    }

    float4 rst;
    if (deg > 0) {
        float inv = 1.0f / sumex;
        rst = make_float4(acc.x * inv, acc.y * inv, acc.z * inv, acc.w * inv);
    } else {
        rst = make_float4(0.f, 0.f, 0.f, 0.f);
    }

    float4 sk = *(const float4*)&g_skip[(size_t)n * 128 + 4 * lane];
    float4 w1 = *(const float4*)&W_gate[4 * lane];
    float4 w2 = *(const float4*)&W_gate[128 + 4 * lane];
    float4 w3 = *(const float4*)&W_gate[256 + 4 * lane];
    float gacc = rst.x * w1.x + rst.y * w1.y + rst.z * w1.z + rst.w * w1.w
               + sk.x * w2.x + sk.y * w2.y + sk.z * w2.z + sk.w * w2.w
               + (rst.x - sk.x) * w3.x + (rst.y - sk.y) * w3.y
               + (rst.z - sk.z) * w3.z + (rst.w - sk.w) * w3.w;
#pragma unroll
    for (int off = 16; off >= 1; off >>= 1)
        gacc += __shfl_xor_sync(0xffffffffu, gacc, off);
    float gate = 1.0f / (1.0f + __expf(-(gacc + b_gate[0])));
    float4 x = make_float4(gate * rst.x + (1.f - gate) * sk.x,
                           gate * rst.y + (1.f - gate) * sk.y,
                           gate * rst.z + (1.f - gate) * sk.z,
                           gate * rst.w + (1.f - gate) * sk.w);

    float s1 = x.x + x.y + x.z + x.w;
    float s2 = x.x * x.x + x.y * x.y + x.z * x.z + x.w * x.w;
#pragma unroll
    for (int off = 16; off >= 1; off >>= 1) {
        s1 += __shfl_xor_sync(0xffffffffu, s1, off);
        s2 += __shfl_xor_sync(0xffffffffu, s2, off);
    }
    float mean = s1 * (1.0f / 128.0f);
    float var = s2 * (1.0f / 128.0f) - mean * mean;
    float inv = rsqrtf(var + 1e-5f);
    float4 g4 = *(const float4*)&ln_g[4 * lane];
    float4 b4 = *(const float4*)&ln_b[4 * lane];
    float alpha = prelu_a[0];
    float y0 = (x.x - mean) * inv * g4.x + b4.x;
    float y1 = (x.y - mean) * inv * g4.y + b4.y;
    float y2 = (x.z - mean) * inv * g4.z + b4.z;
    float y3 = (x.w - mean) * inv * g4.w + b4.w;
    y0 = (y0 >= 0.f) ? y0 : alpha * y0;
    y1 = (y1 >= 0.f) ? y1 : alpha * y1;
    y2 = (y2 >= 0.f) ? y2 : alpha * y2;
    y3 = (y3 >= 0.f) ? y3 : alpha * y3;
    *(float4*)&out[(size_t)n * 128 + 4 * lane] = make_float4(y0, y1, y2, y3);
}

// ---------------- launcher ---------------------------------------------------
extern "C" void kernel_launch(void* const* d_in, const int* in_sizes, int n_in,
                              void* d_out, int out_size) {
    const float* feat    = (const float*)d_in[0];
    const int*   src     = (const int*)d_in[1];
    const int*   dst     = (const int*)d_in[2];
    const float* W_src   = (const float*)d_in[3];
    const float* b_src   = (const float*)d_in[4];
    const float* attn_l  = (const float*)d_in[5];
    const float* attn_r  = (const float*)d_in[6];
    const float* W_skip  = (const float*)d_in[7];
    const float* b_skip  = (const float*)d_in[8];
    const float* W_gate  = (const float*)d_in[9];
    const float* b_gate  = (const float*)d_in[10];
    const float* ln_g    = (const float*)d_in[11];
    const float* ln_b    = (const float*)d_in[12];
    const float* prelu_a = (const float*)d_in[13];
    float* out = (float*)d_out;

    // smem: (64 + 128) * PITCH * 2B = 52224
    const int FAT_SMEM = (64 + 128) * PITCH * (int)sizeof(__half);
    static int smem_set = 0;
    if (!smem_set) {
        cudaFuncSetAttribute(k_fat, cudaFuncAttributeMaxDynamicSharedMemorySize, FAT_SMEM);
        smem_set = 1;
    }

    k_fat<<<FAT_BLKS, 256, FAT_SMEM>>>(feat, attn_l, attn_r,
                                       W_src, b_src, W_skip, b_skip, dst);
    k_scan<<<98, 1024>>>();
    k_fill<<<(EE + 255) / 256, 256>>>(src, dst);
    k_node<<<(NN * 32 + 255) / 256, 256>>>(W_gate, b_gate, ln_g, ln_b, prelu_a, out);
}